// round 12
// baseline (speedup 1.0000x reference)
#include <cuda_runtime.h>
#include <cuda_bf16.h>
#include <cstdint>
#include <cstddef>

// Problem constants
#define B_ 64
#define S_ 512
#define E_ 256
#define H_ 512

// Scan decomposition: 16 clusters x 8 CTAs; each cluster owns 4 batch rows,
// each CTA owns 64 rows of W_hh held in REGISTERS for all 512 steps.
#define BT_ 16     // batch tiles (clusters)
#define BC_ 4      // batch rows per cluster
#define CL_ 8      // CTAs per cluster (j split: 8 * 64 = 512)
#define JL_ 64     // W_hh rows per CTA
#define HPITCH_ 544  // padded floats per batch row: 8 blocks of (64 data + 4 pad)
                     // -> the 8 k-slices start on disjoint bank groups (stride 68 ≡ 4 mod 32)

typedef unsigned long long u64;

// ---------------------------------------------------------------------------
// Packed fp32x2 helpers (Blackwell FFMA2 path: 2x fp32 throughput, full IEEE)
// ---------------------------------------------------------------------------
__device__ __forceinline__ u64 pack2(float lo, float hi) {
    u64 r; asm("mov.b64 %0, {%1, %2};" : "=l"(r) : "f"(lo), "f"(hi)); return r;
}
__device__ __forceinline__ u64 splat2(float x) {
    u64 r; asm("mov.b64 %0, {%1, %1};" : "=l"(r) : "f"(x)); return r;
}
__device__ __forceinline__ void fma2(u64& d, u64 a, u64 b) {
    asm("fma.rn.f32x2 %0, %1, %2, %0;" : "+l"(d) : "l"(a), "l"(b));
}
__device__ __forceinline__ void unpack2(u64 v, float& lo, float& hi) {
    asm("mov.b64 {%0, %1}, %2;" : "=f"(lo), "=f"(hi) : "l"(v));
}

// Fast tanh: 2 MUFU ops, abs error ~1e-7 (vs 1e-3 budget). Large |x| -> exp=inf -> 1.
__device__ __forceinline__ float fast_tanh(float x) {
    float ax = fabsf(x);
    float e  = __expf(ax + ax);
    float r  = 1.0f - __fdividef(2.0f, e + 1.0f);
    return copysignf(r, x);
}

// ---------------------------------------------------------------------------
// Device scratch (no allocations allowed)
// ---------------------------------------------------------------------------
__device__ float g_pre[(size_t)B_ * S_ * H_];   // pre-activations (reused per layer)
__device__ float g_y0[(size_t)B_ * S_ * H_];    // layer-0 outputs
__device__ float g_hsc[2][BT_ * BC_ * H_];      // double-buffered h exchange via L2 (scalar layout)

__device__ __forceinline__ void cluster_sync_() {
    // arrive(.release) / wait(.acquire) at cluster scope: orders the __stcg
    // h-writes before peers' __ldcg h-reads. Also a full intra-CTA barrier.
    asm volatile("barrier.cluster.arrive.aligned;" ::: "memory");
    asm volatile("barrier.cluster.wait.aligned;" ::: "memory");
}

// ---------------------------------------------------------------------------
// GEMM: C[m,n] = sum_k Arow(m)[k] * W[n,k] + ba[n] + bb[n]
// Arow(m) = idx ? emb[idx[m]] : A[m]   (fused embedding gather)
// 128x128x16 tile, 256 threads, 8x8 microtile, packed f32x2 accumulators.
// ---------------------------------------------------------------------------
__global__ void __launch_bounds__(256) gemm_tn_kernel(
    const float* __restrict__ A, const int* __restrict__ idx, int lda,
    const float* __restrict__ W, const float* __restrict__ ba,
    const float* __restrict__ bb, float* __restrict__ C, int N, int K)
{
    __shared__ float As[16][136];
    __shared__ float Bs[16][136];
    __shared__ int srcs[128];

    const int tid = threadIdx.x;
    const int m0 = blockIdx.y * 128;
    const int n0 = blockIdx.x * 128;

    if (idx != nullptr && tid < 128) srcs[tid] = idx[m0 + tid];
    __syncthreads();

    const int lm = tid >> 1;          // 0..127 : row this thread loads
    const int lk = (tid & 1) * 8;     // 0 or 8 : k offset (two float4s)
    const float* arow = (idx != nullptr) ? (A + (size_t)srcs[lm] * (size_t)lda)
                                         : (A + (size_t)(m0 + lm) * (size_t)lda);
    const float* brow = W + (size_t)(n0 + lm) * (size_t)K;

    const int iy = tid >> 4;          // 0..15 : row group (8 rows)
    const int ix = tid & 15;          // 0..15 : col group (8 cols = 4 f32x2)

    u64 acc[8][4];
#pragma unroll
    for (int r = 0; r < 8; ++r)
#pragma unroll
        for (int c = 0; c < 4; ++c) acc[r][c] = 0ull;

    for (int k0 = 0; k0 < K; k0 += 16) {
        float4 av0 = *(const float4*)(arow + k0 + lk);
        float4 av1 = *(const float4*)(arow + k0 + lk + 4);
        float4 bv0 = *(const float4*)(brow + k0 + lk);
        float4 bv1 = *(const float4*)(brow + k0 + lk + 4);
        __syncthreads();
        As[lk + 0][lm] = av0.x; As[lk + 1][lm] = av0.y;
        As[lk + 2][lm] = av0.z; As[lk + 3][lm] = av0.w;
        As[lk + 4][lm] = av1.x; As[lk + 5][lm] = av1.y;
        As[lk + 6][lm] = av1.z; As[lk + 7][lm] = av1.w;
        Bs[lk + 0][lm] = bv0.x; Bs[lk + 1][lm] = bv0.y;
        Bs[lk + 2][lm] = bv0.z; Bs[lk + 3][lm] = bv0.w;
        Bs[lk + 4][lm] = bv1.x; Bs[lk + 5][lm] = bv1.y;
        Bs[lk + 6][lm] = bv1.z; Bs[lk + 7][lm] = bv1.w;
        __syncthreads();
#pragma unroll
        for (int k = 0; k < 16; ++k) {
            float4 a0 = *(const float4*)&As[k][iy * 8];
            float4 a1 = *(const float4*)&As[k][iy * 8 + 4];
            ulonglong2 bq0 = *(const ulonglong2*)&Bs[k][ix * 8];
            ulonglong2 bq1 = *(const ulonglong2*)&Bs[k][ix * 8 + 4];
            u64 s;
            s = splat2(a0.x);
            fma2(acc[0][0], s, bq0.x); fma2(acc[0][1], s, bq0.y);
            fma2(acc[0][2], s, bq1.x); fma2(acc[0][3], s, bq1.y);
            s = splat2(a0.y);
            fma2(acc[1][0], s, bq0.x); fma2(acc[1][1], s, bq0.y);
            fma2(acc[1][2], s, bq1.x); fma2(acc[1][3], s, bq1.y);
            s = splat2(a0.z);
            fma2(acc[2][0], s, bq0.x); fma2(acc[2][1], s, bq0.y);
            fma2(acc[2][2], s, bq1.x); fma2(acc[2][3], s, bq1.y);
            s = splat2(a0.w);
            fma2(acc[3][0], s, bq0.x); fma2(acc[3][1], s, bq0.y);
            fma2(acc[3][2], s, bq1.x); fma2(acc[3][3], s, bq1.y);
            s = splat2(a1.x);
            fma2(acc[4][0], s, bq0.x); fma2(acc[4][1], s, bq0.y);
            fma2(acc[4][2], s, bq1.x); fma2(acc[4][3], s, bq1.y);
            s = splat2(a1.y);
            fma2(acc[5][0], s, bq0.x); fma2(acc[5][1], s, bq0.y);
            fma2(acc[5][2], s, bq1.x); fma2(acc[5][3], s, bq1.y);
            s = splat2(a1.z);
            fma2(acc[6][0], s, bq0.x); fma2(acc[6][1], s, bq0.y);
            fma2(acc[6][2], s, bq1.x); fma2(acc[6][3], s, bq1.y);
            s = splat2(a1.w);
            fma2(acc[7][0], s, bq0.x); fma2(acc[7][1], s, bq0.y);
            fma2(acc[7][2], s, bq1.x); fma2(acc[7][3], s, bq1.y);
        }
    }

    const int n = n0 + ix * 8;
    float bias[8];
#pragma unroll
    for (int c = 0; c < 8; ++c) bias[c] = ba[n + c] + bb[n + c];

#pragma unroll
    for (int r = 0; r < 8; ++r) {
        float v[8];
#pragma unroll
        for (int c = 0; c < 4; ++c) unpack2(acc[r][c], v[2 * c], v[2 * c + 1]);
        float4 o0 = make_float4(v[0] + bias[0], v[1] + bias[1], v[2] + bias[2], v[3] + bias[3]);
        float4 o1 = make_float4(v[4] + bias[4], v[5] + bias[5], v[6] + bias[6], v[7] + bias[7]);
        float* crow = C + (size_t)(m0 + iy * 8 + r) * (size_t)N + n;
        *(float4*)(crow)     = o0;
        *(float4*)(crow + 4) = o1;
    }
}

// ---------------------------------------------------------------------------
// Recurrent scan: h_t = tanh(pre[:,t,:] + h_{t-1} @ W_hh^T)
// Grid (CL_, BT_), cluster (CL_,1,1), 512 threads (16 warps).
// Warp w owns j rows [w*4, w*4+4); within the warp, jsub = lane>>3 picks the
// row and ks = lane&7 is an 8-way k-split (64 k's each). W held in registers
// as pre-packed f32x2 k-pairs -> compute = 64 LDS.128 + 128 FFMA2 per thread.
// Reduction over ks via 3 shfl.bfly rounds (no smem). Tail parallel across
// all 16 warps (lane r<4 handles batch lane r of its j row).
// h exchanged between cluster CTAs via L2 (stcg/ldcg) + cluster barrier.
// ---------------------------------------------------------------------------
__global__ void __launch_bounds__(512, 1) __cluster_dims__(CL_, 1, 1)
rnn_scan_kernel(const float* __restrict__ pre, const float* __restrict__ Whh,
                float* __restrict__ y, float* __restrict__ hlast)
{
    __shared__ float h_sh[2][BC_ * HPITCH_];   // double-buffered h, k-major per batch row

    const int tid  = threadIdx.x;
    const int w    = tid >> 5;
    const int lane = tid & 31;
    const int jsub = lane >> 3;
    const int ks   = lane & 7;
    const int rank = blockIdx.x;   // 0..7  (j slice)
    const int bt   = blockIdx.y;   // 0..15 (batch tile)
    const int jg   = rank * JL_ + w * 4 + jsub;

    // --- W row slice into registers, packed as f32x2 k-pairs (one-time) ---
    u64 wp[32];
    {
        const float4* wsrc = (const float4*)(Whh + (size_t)jg * H_ + ks * 64);
#pragma unroll
        for (int i = 0; i < 16; ++i) {
            float4 v = __ldg(&wsrc[i]);
            wp[2 * i]     = pack2(v.x, v.y);
            wp[2 * i + 1] = pack2(v.z, v.w);
        }
    }
    // h_0 = 0
    for (int i = tid; i < BC_ * HPITCH_; i += 512) h_sh[0][i] = 0.f;
    __syncthreads();

    const int  r      = ks;                 // batch lane this thread finalizes (if r<4)
    const bool active = (r < BC_);
    const size_t pbase0 = ((size_t)(bt * BC_ + r) * S_) * H_ + jg;   // + t*H_

    // pre prefetch pipeline (2-deep: pre is h-independent)
    float p_cur = active ? __ldg(pre + pbase0) : 0.f;

    for (int t = 0; t < S_; ++t) {
        float p_nxt = 0.f;
        if (active && t + 1 < S_) p_nxt = __ldg(pre + pbase0 + (size_t)(t + 1) * H_);

        const float* hb = h_sh[t & 1];
        const ulonglong2* h0 = (const ulonglong2*)(hb + 0 * HPITCH_ + ks * 68);
        const ulonglong2* h1 = (const ulonglong2*)(hb + 1 * HPITCH_ + ks * 68);
        const ulonglong2* h2 = (const ulonglong2*)(hb + 2 * HPITCH_ + ks * 68);
        const ulonglong2* h3 = (const ulonglong2*)(hb + 3 * HPITCH_ + ks * 68);

        u64 a0 = 0ull, a1 = 0ull, a2 = 0ull, a3 = 0ull;   // k-pair partials per batch lane
#pragma unroll
        for (int i = 0; i < 16; ++i) {
            const u64 wlo = wp[2 * i], whi = wp[2 * i + 1];
            ulonglong2 x;
            x = h0[i]; fma2(a0, wlo, x.x); fma2(a0, whi, x.y);
            x = h1[i]; fma2(a1, wlo, x.x); fma2(a1, whi, x.y);
            x = h2[i]; fma2(a2, wlo, x.x); fma2(a2, whi, x.y);
            x = h3[i]; fma2(a3, wlo, x.x); fma2(a3, whi, x.y);
        }

        // fold k-pair halves, then shfl-reduce over the 8 ks lanes
        float s0, s1, s2, s3, hi;
        unpack2(a0, s0, hi); s0 += hi;
        unpack2(a1, s1, hi); s1 += hi;
        unpack2(a2, s2, hi); s2 += hi;
        unpack2(a3, s3, hi); s3 += hi;
#pragma unroll
        for (int m = 4; m > 0; m >>= 1) {
            s0 += __shfl_xor_sync(0xFFFFFFFFu, s0, m);
            s1 += __shfl_xor_sync(0xFFFFFFFFu, s1, m);
            s2 += __shfl_xor_sync(0xFFFFFFFFu, s2, m);
            s3 += __shfl_xor_sync(0xFFFFFFFFu, s3, m);
        }

        if (active) {
            const float sv = (r == 0) ? s0 : (r == 1) ? s1 : (r == 2) ? s2 : s3;
            const float v  = fast_tanh(sv + p_cur);
            y[pbase0 + (size_t)t * H_] = v;
            __stcg(&g_hsc[(t + 1) & 1][(bt * BC_ + r) * H_ + jg], v);
            if (t == S_ - 1) hlast[(size_t)(bt * BC_ + r) * H_ + jg] = v;
        }
        p_cur = p_nxt;

        cluster_sync_();   // release h-writes / acquire for peers' reads
        if (t + 1 < S_) {
            // refill padded smem h from L2: one LDG.128 + one STS.128 per thread
            const int b  = tid >> 7;
            const int k0 = (tid & 127) * 4;
            float4 hv = __ldcg((const float4*)&g_hsc[(t + 1) & 1][(bt * BC_ + b) * H_ + k0]);
            *(float4*)&h_sh[(t + 1) & 1][b * HPITCH_ + (k0 >> 6) * 68 + (k0 & 63)] = hv;
            __syncthreads();
        }
    }
}

// ---------------------------------------------------------------------------
// Launch
// Inputs: src, emb, W_ih0, W_hh0, b_ih0, b_hh0, W_ih1, W_hh1, b_ih1, b_hh1
// Output: y1 [B,S,H] followed by hidden [2,B,H]
// ---------------------------------------------------------------------------
extern "C" void kernel_launch(void* const* d_in, const int* in_sizes, int n_in,
                              void* d_out, int out_size)
{
    (void)in_sizes; (void)n_in; (void)out_size;
    const int*   src  = (const int*)d_in[0];
    const float* emb  = (const float*)d_in[1];
    const float* Wih0 = (const float*)d_in[2];
    const float* Whh0 = (const float*)d_in[3];
    const float* bih0 = (const float*)d_in[4];
    const float* bhh0 = (const float*)d_in[5];
    const float* Wih1 = (const float*)d_in[6];
    const float* Whh1 = (const float*)d_in[7];
    const float* bih1 = (const float*)d_in[8];
    const float* bhh1 = (const float*)d_in[9];

    float* out = (float*)d_out;
    float* y1  = out;
    float* hid = out + (size_t)B_ * S_ * H_;

    float *pre = nullptr, *y0 = nullptr;
    cudaGetSymbolAddress((void**)&pre, g_pre);
    cudaGetSymbolAddress((void**)&y0,  g_y0);

    const dim3 gemm_blk(256);
    const dim3 scan_blk(512);
    const dim3 gemm_grid(H_ / 128, (B_ * S_) / 128);
    const dim3 scan_grid(CL_, BT_);

    // Layer 0: fused embedding-gather GEMM -> pre, then scan -> y0, h_last0
    gemm_tn_kernel<<<gemm_grid, gemm_blk>>>(emb, src, E_, Wih0, bih0, bhh0, pre, H_, E_);
    rnn_scan_kernel<<<scan_grid, scan_blk>>>(pre, Whh0, y0, hid);

    // Layer 1: plain GEMM -> pre (reused), then scan -> y1 (d_out), h_last1
    gemm_tn_kernel<<<gemm_grid, gemm_blk>>>(y0, nullptr, H_, Wih1, bih1, bhh1, pre, H_, H_);
    rnn_scan_kernel<<<scan_grid, scan_blk>>>(pre, Whh1, y1, hid + (size_t)B_ * H_);
}

// round 13
// speedup vs baseline: 2.0289x; 2.0289x over previous
#include <cuda_runtime.h>
#include <cuda_bf16.h>
#include <cstdint>
#include <cstddef>

// Problem constants
#define B_ 64
#define S_ 512
#define E_ 256
#define H_ 512

// Scan decomposition: 16 clusters x 8 CTAs; each cluster owns 4 batch rows,
// each CTA owns 64 rows of W_hh (2 rows/thread) held in REGISTERS.
#define BT_ 16       // batch tiles (clusters)
#define BC_ 4        // batch rows per cluster
#define CL_ 8        // CTAs per cluster (j split: 8 * 64 = 512)
#define JL_ 64       // W_hh rows per CTA
#define HP_ 544      // h pitch per batch row: 8 blocks of (64 data + 4 pad) floats
                     // -> ks-slices start 272B apart = bank offset 4 -> conflict-free LDS.128
#define RP_ 260      // red pitch per ks block: 64*4 + 4 floats (STS.128 lands 4 words/bank = floor)

typedef unsigned long long u64;

// ---------------------------------------------------------------------------
// Packed fp32x2 helpers (Blackwell FFMA2 path: 2x fp32 throughput, full IEEE)
// ---------------------------------------------------------------------------
__device__ __forceinline__ u64 pack2(float lo, float hi) {
    u64 r; asm("mov.b64 %0, {%1, %2};" : "=l"(r) : "f"(lo), "f"(hi)); return r;
}
__device__ __forceinline__ u64 splat2(float x) {
    u64 r; asm("mov.b64 %0, {%1, %1};" : "=l"(r) : "f"(x)); return r;
}
__device__ __forceinline__ void fma2(u64& d, u64 a, u64 b) {
    asm("fma.rn.f32x2 %0, %1, %2, %0;" : "+l"(d) : "l"(a), "l"(b));
}
__device__ __forceinline__ void unpack2(u64 v, float& lo, float& hi) {
    asm("mov.b64 {%0, %1}, %2;" : "=f"(lo), "=f"(hi) : "l"(v));
}

// Fast tanh: 2 MUFU ops, abs error ~1e-7. Large |x| -> exp=inf -> 1.
__device__ __forceinline__ float fast_tanh(float x) {
    float ax = fabsf(x);
    float e  = __expf(ax + ax);
    float r  = 1.0f - __fdividef(2.0f, e + 1.0f);
    return copysignf(r, x);
}

// ---------------------------------------------------------------------------
// DSMEM / mbarrier primitives
// ---------------------------------------------------------------------------
__device__ __forceinline__ uint32_t smem_u32(const void* p) {
    uint32_t a;
    asm("{ .reg .u64 t; cvta.to.shared.u64 t, %1; cvt.u32.u64 %0, t; }"
        : "=r"(a) : "l"(p));
    return a;
}
__device__ __forceinline__ uint32_t mapa_(uint32_t addr, uint32_t rank) {
    uint32_t r;
    asm("mapa.shared::cluster.u32 %0, %1, %2;" : "=r"(r) : "r"(addr), "r"(rank));
    return r;
}
__device__ __forceinline__ void mbar_init(uint32_t mbar, uint32_t count) {
    asm volatile("mbarrier.init.shared.b64 [%0], %1;" :: "r"(mbar), "r"(count) : "memory");
}
__device__ __forceinline__ void mbar_arrive_expect_tx(uint32_t mbar, uint32_t bytes) {
    asm volatile("mbarrier.arrive.expect_tx.shared.b64 _, [%0], %1;"
                 :: "r"(mbar), "r"(bytes) : "memory");
}
__device__ __forceinline__ void mbar_wait(uint32_t mbar, uint32_t parity) {
    asm volatile(
        "{\n\t"
        ".reg .pred P1;\n\t"
        "WAIT_LOOP_%=:\n\t"
        "mbarrier.try_wait.parity.acquire.cluster.shared::cta.b64 P1, [%0], %1, 0x989680;\n\t"
        "@P1 bra.uni WAIT_DONE_%=;\n\t"
        "bra.uni WAIT_LOOP_%=;\n\t"
        "WAIT_DONE_%=:\n\t"
        "}"
        :: "r"(mbar), "r"(parity) : "memory");
}
// Store one b32 into a peer CTA's smem; completion counts 4 bytes on the peer's mbarrier.
__device__ __forceinline__ void st_async_b32(uint32_t raddr, uint32_t val, uint32_t rmbar) {
    asm volatile("st.async.shared::cluster.mbarrier::complete_tx::bytes.b32 [%0], %1, [%2];"
                 :: "r"(raddr), "r"(val), "r"(rmbar) : "memory");
}
#define CLUSTER_SYNC_() do { \
    asm volatile("barrier.cluster.arrive.aligned;" ::: "memory"); \
    asm volatile("barrier.cluster.wait.aligned;" ::: "memory"); \
} while (0)

// ---------------------------------------------------------------------------
// Device scratch (no allocations allowed)
// ---------------------------------------------------------------------------
__device__ float g_pre[(size_t)B_ * S_ * H_];   // pre-activations (reused per layer)
__device__ float g_y0[(size_t)B_ * S_ * H_];    // layer-0 outputs

// ---------------------------------------------------------------------------
// GEMM: C[m,n] = sum_k Arow(m)[k] * W[n,k] + ba[n] + bb[n]   (unchanged, proven)
// ---------------------------------------------------------------------------
__global__ void __launch_bounds__(256) gemm_tn_kernel(
    const float* __restrict__ A, const int* __restrict__ idx, int lda,
    const float* __restrict__ W, const float* __restrict__ ba,
    const float* __restrict__ bb, float* __restrict__ C, int N, int K)
{
    __shared__ float As[16][136];
    __shared__ float Bs[16][136];
    __shared__ int srcs[128];

    const int tid = threadIdx.x;
    const int m0 = blockIdx.y * 128;
    const int n0 = blockIdx.x * 128;

    if (idx != nullptr && tid < 128) srcs[tid] = idx[m0 + tid];
    __syncthreads();

    const int lm = tid >> 1;
    const int lk = (tid & 1) * 8;
    const float* arow = (idx != nullptr) ? (A + (size_t)srcs[lm] * (size_t)lda)
                                         : (A + (size_t)(m0 + lm) * (size_t)lda);
    const float* brow = W + (size_t)(n0 + lm) * (size_t)K;

    const int iy = tid >> 4;
    const int ix = tid & 15;

    u64 acc[8][4];
#pragma unroll
    for (int r = 0; r < 8; ++r)
#pragma unroll
        for (int c = 0; c < 4; ++c) acc[r][c] = 0ull;

    for (int k0 = 0; k0 < K; k0 += 16) {
        float4 av0 = *(const float4*)(arow + k0 + lk);
        float4 av1 = *(const float4*)(arow + k0 + lk + 4);
        float4 bv0 = *(const float4*)(brow + k0 + lk);
        float4 bv1 = *(const float4*)(brow + k0 + lk + 4);
        __syncthreads();
        As[lk + 0][lm] = av0.x; As[lk + 1][lm] = av0.y;
        As[lk + 2][lm] = av0.z; As[lk + 3][lm] = av0.w;
        As[lk + 4][lm] = av1.x; As[lk + 5][lm] = av1.y;
        As[lk + 6][lm] = av1.z; As[lk + 7][lm] = av1.w;
        Bs[lk + 0][lm] = bv0.x; Bs[lk + 1][lm] = bv0.y;
        Bs[lk + 2][lm] = bv0.z; Bs[lk + 3][lm] = bv0.w;
        Bs[lk + 4][lm] = bv1.x; Bs[lk + 5][lm] = bv1.y;
        Bs[lk + 6][lm] = bv1.z; Bs[lk + 7][lm] = bv1.w;
        __syncthreads();
#pragma unroll
        for (int k = 0; k < 16; ++k) {
            float4 a0 = *(const float4*)&As[k][iy * 8];
            float4 a1 = *(const float4*)&As[k][iy * 8 + 4];
            ulonglong2 bq0 = *(const ulonglong2*)&Bs[k][ix * 8];
            ulonglong2 bq1 = *(const ulonglong2*)&Bs[k][ix * 8 + 4];
            u64 s;
            s = splat2(a0.x);
            fma2(acc[0][0], s, bq0.x); fma2(acc[0][1], s, bq0.y);
            fma2(acc[0][2], s, bq1.x); fma2(acc[0][3], s, bq1.y);
            s = splat2(a0.y);
            fma2(acc[1][0], s, bq0.x); fma2(acc[1][1], s, bq0.y);
            fma2(acc[1][2], s, bq1.x); fma2(acc[1][3], s, bq1.y);
            s = splat2(a0.z);
            fma2(acc[2][0], s, bq0.x); fma2(acc[2][1], s, bq0.y);
            fma2(acc[2][2], s, bq1.x); fma2(acc[2][3], s, bq1.y);
            s = splat2(a0.w);
            fma2(acc[3][0], s, bq0.x); fma2(acc[3][1], s, bq0.y);
            fma2(acc[3][2], s, bq1.x); fma2(acc[3][3], s, bq1.y);
            s = splat2(a1.x);
            fma2(acc[4][0], s, bq0.x); fma2(acc[4][1], s, bq0.y);
            fma2(acc[4][2], s, bq1.x); fma2(acc[4][3], s, bq1.y);
            s = splat2(a1.y);
            fma2(acc[5][0], s, bq0.x); fma2(acc[5][1], s, bq0.y);
            fma2(acc[5][2], s, bq1.x); fma2(acc[5][3], s, bq1.y);
            s = splat2(a1.z);
            fma2(acc[6][0], s, bq0.x); fma2(acc[6][1], s, bq0.y);
            fma2(acc[6][2], s, bq1.x); fma2(acc[6][3], s, bq1.y);
            s = splat2(a1.w);
            fma2(acc[7][0], s, bq0.x); fma2(acc[7][1], s, bq0.y);
            fma2(acc[7][2], s, bq1.x); fma2(acc[7][3], s, bq1.y);
        }
    }

    const int n = n0 + ix * 8;
    float bias[8];
#pragma unroll
    for (int c = 0; c < 8; ++c) bias[c] = ba[n + c] + bb[n + c];

#pragma unroll
    for (int r = 0; r < 8; ++r) {
        float v[8];
#pragma unroll
        for (int c = 0; c < 4; ++c) unpack2(acc[r][c], v[2 * c], v[2 * c + 1]);
        float4 o0 = make_float4(v[0] + bias[0], v[1] + bias[1], v[2] + bias[2], v[3] + bias[3]);
        float4 o1 = make_float4(v[4] + bias[4], v[5] + bias[5], v[6] + bias[6], v[7] + bias[7]);
        float* crow = C + (size_t)(m0 + iy * 8 + r) * (size_t)N + n;
        *(float4*)(crow)     = o0;
        *(float4*)(crow + 4) = o1;
    }
}

// ---------------------------------------------------------------------------
// Recurrent scan: h_t = tanh(pre[:,t,:] + h_{t-1} @ W_hh^T)
// Grid (CL_, BT_), cluster (CL_,1,1), 256 threads (8 warps).
// Compute map: jg = tid>>3 (32 groups of 2 j-rows), ks = tid&7 (64-k slice).
//   W: 2 rows x 64 k = 64 u64 k-pairs in REGISTERS (loaded once).
//   h: 64 k x 4 b from padded smem -> 64 LDS.128/thread (conflict-free).
//   8-way k-split reduced via padded smem (red), one __syncthreads.
// Finalize map: fj = tid&63 (j row), fb = tid>>6 (batch lane); each of the
//   256 threads produces ONE h value and st.async-broadcasts it into all 8
//   cluster CTAs' next-parity h buffer; receivers wait on a parity mbarrier
//   armed with expect_tx = 2048 values * 4 B = 8192 B.
// ---------------------------------------------------------------------------
__global__ void __launch_bounds__(256, 1) __cluster_dims__(CL_, 1, 1)
rnn_scan_kernel(const float* __restrict__ pre, const float* __restrict__ Whh,
                float* __restrict__ y, float* __restrict__ hlast)
{
    __shared__ float h_sh[2][BC_ * HP_];          // double-buffered h (17.4 KB)
    __shared__ float red[2][8 * RP_];             // double-buffered partials (16.6 KB)
    __shared__ __align__(8) u64 bars[2];          // parity mbarriers

    const int tid  = threadIdx.x;
    const int rank = blockIdx.x;   // 0..7  (j slice)
    const int bt   = blockIdx.y;   // 0..15 (batch tile)
    const int jg   = tid >> 3;     // 0..31 (2 j-rows each)
    const int ks   = tid & 7;      // 0..7  (64-k slice)

    const uint32_t bar0 = smem_u32(&bars[0]);
    const uint32_t bar1 = smem_u32(&bars[1]);

    if (tid == 0) {
        mbar_init(bar0, 1);
        mbar_init(bar1, 1);
        mbar_arrive_expect_tx(bar1, 8192);   // first use: h_1 at t=1
        mbar_arrive_expect_tx(bar0, 8192);   // first use: h_2 at t=2
    }
    // h_0 = 0 (buffer 0); buffer 1 fully overwritten by st.async before use
    for (int i = tid; i < BC_ * HP_; i += 256) { h_sh[0][i] = 0.f; h_sh[1][i] = 0.f; }
    __syncthreads();
    CLUSTER_SYNC_();   // all CTAs' mbarriers initialized before any st.async

    // --- W slice into registers: rows {2jg, 2jg+1}, k in [ks*64, ks*64+64) ---
    u64 wA[32], wB[32];
    {
        const float4* wa = (const float4*)(Whh + (size_t)(rank * JL_ + 2 * jg) * H_ + ks * 64);
        const float4* wb = (const float4*)(Whh + (size_t)(rank * JL_ + 2 * jg + 1) * H_ + ks * 64);
#pragma unroll
        for (int i = 0; i < 16; ++i) {
            float4 va = __ldg(wa + i);
            float4 vb = __ldg(wb + i);
            wA[2 * i] = pack2(va.x, va.y); wA[2 * i + 1] = pack2(va.z, va.w);
            wB[2 * i] = pack2(vb.x, vb.y); wB[2 * i + 1] = pack2(vb.z, vb.w);
        }
    }

    // Finalize identity: one output value per thread
    const int fj = tid & 63;
    const int fb = tid >> 6;
    const size_t pbase = ((size_t)(bt * BC_ + fb) * S_) * H_ + rank * JL_ + fj;
    // st.async destination (same offset in every CTA): next-parity buffer slot
    const uint32_t hoff[2] = {
        smem_u32(&h_sh[0][fb * HP_ + rank * 68 + fj]),
        smem_u32(&h_sh[1][fb * HP_ + rank * 68 + fj])
    };

    for (int t = 0; t < S_; ++t) {
        const int q = t & 1;
        // prefetch pre[t] before the wait: DRAM latency overlaps mbarrier wait
        const float p = __ldg(pre + pbase + (size_t)t * H_);

        if (t > 0) {
            mbar_wait(q ? bar1 : bar0, ((unsigned)(t - 1) >> 1) & 1);
            if (tid == 0 && t + 2 < S_)
                mbar_arrive_expect_tx(q ? bar1 : bar0, 8192);  // re-arm for t+2
        }

        // --- matvec: 2 j-rows x 4 b over this thread's 64 k ---
        const float* hb = h_sh[q];
        const char* h0 = (const char*)(hb + 0 * HP_ + ks * 68);
        const char* h1 = (const char*)(hb + 1 * HP_ + ks * 68);
        const char* h2 = (const char*)(hb + 2 * HP_ + ks * 68);
        const char* h3 = (const char*)(hb + 3 * HP_ + ks * 68);

        u64 aA0 = 0, aA1 = 0, aA2 = 0, aA3 = 0;   // row A, batches 0..3
        u64 aB0 = 0, aB1 = 0, aB2 = 0, aB3 = 0;   // row B
#pragma unroll
        for (int ii = 0; ii < 16; ++ii) {
            ulonglong2 x0 = *(const ulonglong2*)(h0 + ii * 16);
            ulonglong2 x1 = *(const ulonglong2*)(h1 + ii * 16);
            ulonglong2 x2 = *(const ulonglong2*)(h2 + ii * 16);
            ulonglong2 x3 = *(const ulonglong2*)(h3 + ii * 16);
            const u64 wa0 = wA[2 * ii], wa1 = wA[2 * ii + 1];
            const u64 wb0 = wB[2 * ii], wb1 = wB[2 * ii + 1];
            fma2(aA0, wa0, x0.x); fma2(aA0, wa1, x0.y);
            fma2(aA1, wa0, x1.x); fma2(aA1, wa1, x1.y);
            fma2(aA2, wa0, x2.x); fma2(aA2, wa1, x2.y);
            fma2(aA3, wa0, x3.x); fma2(aA3, wa1, x3.y);
            fma2(aB0, wb0, x0.x); fma2(aB0, wb1, x0.y);
            fma2(aB1, wb0, x1.x); fma2(aB1, wb1, x1.y);
            fma2(aB2, wb0, x2.x); fma2(aB2, wb1, x2.y);
            fma2(aB3, wb0, x3.x); fma2(aB3, wb1, x3.y);
        }

        // fold k-pair halves -> 8 scalars, stash into red[q]
        float lo, hi;
        float4 vA, vB;
        unpack2(aA0, lo, hi); vA.x = lo + hi;
        unpack2(aA1, lo, hi); vA.y = lo + hi;
        unpack2(aA2, lo, hi); vA.z = lo + hi;
        unpack2(aA3, lo, hi); vA.w = lo + hi;
        unpack2(aB0, lo, hi); vB.x = lo + hi;
        unpack2(aB1, lo, hi); vB.y = lo + hi;
        unpack2(aB2, lo, hi); vB.z = lo + hi;
        unpack2(aB3, lo, hi); vB.w = lo + hi;
        *(float4*)&red[q][ks * RP_ + (2 * jg + 0) * 4] = vA;
        *(float4*)&red[q][ks * RP_ + (2 * jg + 1) * 4] = vB;
        __syncthreads();

        // --- finalize: sum 8 partials, tanh, store, broadcast ---
        float s = p;
#pragma unroll
        for (int g = 0; g < 8; ++g) s += red[q][g * RP_ + fj * 4 + fb];
        const float v = fast_tanh(s);
        y[pbase + (size_t)t * H_] = v;

        if (t == S_ - 1) {
            hlast[(size_t)(bt * BC_ + fb) * H_ + rank * JL_ + fj] = v;
        } else {
            const uint32_t laddr = hoff[(t + 1) & 1];
            const uint32_t lbar  = ((t + 1) & 1) ? bar1 : bar0;
            const uint32_t uv    = __float_as_uint(v);
#pragma unroll
            for (uint32_t c = 0; c < CL_; ++c)
                st_async_b32(mapa_(laddr, c), uv, mapa_(lbar, c));
        }
    }
}

// ---------------------------------------------------------------------------
// Launch
// Inputs: src, emb, W_ih0, W_hh0, b_ih0, b_hh0, W_ih1, W_hh1, b_ih1, b_hh1
// Output: y1 [B,S,H] followed by hidden [2,B,H]
// ---------------------------------------------------------------------------
extern "C" void kernel_launch(void* const* d_in, const int* in_sizes, int n_in,
                              void* d_out, int out_size)
{
    (void)in_sizes; (void)n_in; (void)out_size;
    const int*   src  = (const int*)d_in[0];
    const float* emb  = (const float*)d_in[1];
    const float* Wih0 = (const float*)d_in[2];
    const float* Whh0 = (const float*)d_in[3];
    const float* bih0 = (const float*)d_in[4];
    const float* bhh0 = (const float*)d_in[5];
    const float* Wih1 = (const float*)d_in[6];
    const float* Whh1 = (const float*)d_in[7];
    const float* bih1 = (const float*)d_in[8];
    const float* bhh1 = (const float*)d_in[9];

    float* out = (float*)d_out;
    float* y1  = out;
    float* hid = out + (size_t)B_ * S_ * H_;

    float *pre = nullptr, *y0 = nullptr;
    cudaGetSymbolAddress((void**)&pre, g_pre);
    cudaGetSymbolAddress((void**)&y0,  g_y0);

    const dim3 gemm_blk(256);
    const dim3 scan_blk(256);
    const dim3 gemm_grid(H_ / 128, (B_ * S_) / 128);
    const dim3 scan_grid(CL_, BT_);

    // Layer 0: fused embedding-gather GEMM -> pre, then scan -> y0, h_last0
    gemm_tn_kernel<<<gemm_grid, gemm_blk>>>(emb, src, E_, Wih0, bih0, bhh0, pre, H_, E_);
    rnn_scan_kernel<<<scan_grid, scan_blk>>>(pre, Whh0, y0, hid);

    // Layer 1: plain GEMM -> pre (reused), then scan -> y1 (d_out), h_last1
    gemm_tn_kernel<<<gemm_grid, gemm_blk>>>(y0, nullptr, H_, Wih1, bih1, bhh1, pre, H_, H_);
    rnn_scan_kernel<<<scan_grid, scan_blk>>>(pre, Whh1, y1, hid + (size_t)B_ * H_);
}

// round 16
// speedup vs baseline: 2.0385x; 1.0047x over previous
#include <cuda_runtime.h>
#include <cuda_bf16.h>
#include <cstdint>
#include <cstddef>

// Problem constants
#define B_ 64
#define S_ 512
#define E_ 256
#define H_ 512

// Scan decomposition: 16 clusters x 8 CTAs; each cluster owns 4 batch rows,
// split into TWO independent 2-row sub-problems (software-pipelined to hide
// the DSMEM exchange latency). Each CTA owns 64 rows of W_hh in REGISTERS.
#define BT_ 16       // batch tiles (clusters)
#define BC_ 4        // batch rows per cluster (2 subs x 2 lanes)
#define CL_ 8        // CTAs per cluster (j split: 8 * 64 = 512)
#define JL_ 64       // W_hh rows per CTA
#define HROW_ 544    // h floats per batch row: 8 blocks of (64 data + 4 pad)
#define HPS_ 1088    // per-sub per-parity h buffer: 2 rows * HROW_
#define RP2_ 132     // red pitch per ks block: 64 j * 2 lanes + 4 pad
                     // MUST be multiple of 4 (float4 stores) and ≡4 mod 32 (banks)

typedef unsigned long long u64;

// ---------------------------------------------------------------------------
// Packed fp32x2 helpers (Blackwell FFMA2 path: 2x fp32 throughput, full IEEE)
// ---------------------------------------------------------------------------
__device__ __forceinline__ u64 pack2(float lo, float hi) {
    u64 r; asm("mov.b64 %0, {%1, %2};" : "=l"(r) : "f"(lo), "f"(hi)); return r;
}
__device__ __forceinline__ u64 splat2(float x) {
    u64 r; asm("mov.b64 %0, {%1, %1};" : "=l"(r) : "f"(x)); return r;
}
__device__ __forceinline__ void fma2(u64& d, u64 a, u64 b) {
    asm("fma.rn.f32x2 %0, %1, %2, %0;" : "+l"(d) : "l"(a), "l"(b));
}
__device__ __forceinline__ void unpack2(u64 v, float& lo, float& hi) {
    asm("mov.b64 {%0, %1}, %2;" : "=f"(lo), "=f"(hi) : "l"(v));
}

// Fast tanh: 2 MUFU ops, abs error ~1e-7. Large |x| -> exp=inf -> 1.
__device__ __forceinline__ float fast_tanh(float x) {
    float ax = fabsf(x);
    float e  = __expf(ax + ax);
    float r  = 1.0f - __fdividef(2.0f, e + 1.0f);
    return copysignf(r, x);
}

// ---------------------------------------------------------------------------
// DSMEM / mbarrier primitives
// ---------------------------------------------------------------------------
__device__ __forceinline__ uint32_t smem_u32(const void* p) {
    uint32_t a;
    asm("{ .reg .u64 t; cvta.to.shared.u64 t, %1; cvt.u32.u64 %0, t; }"
        : "=r"(a) : "l"(p));
    return a;
}
__device__ __forceinline__ uint32_t mapa_(uint32_t addr, uint32_t rank) {
    uint32_t r;
    asm("mapa.shared::cluster.u32 %0, %1, %2;" : "=r"(r) : "r"(addr), "r"(rank));
    return r;
}
__device__ __forceinline__ void mbar_init(uint32_t mbar, uint32_t count) {
    asm volatile("mbarrier.init.shared.b64 [%0], %1;" :: "r"(mbar), "r"(count) : "memory");
}
__device__ __forceinline__ void mbar_arrive_expect_tx(uint32_t mbar, uint32_t bytes) {
    asm volatile("mbarrier.arrive.expect_tx.shared.b64 _, [%0], %1;"
                 :: "r"(mbar), "r"(bytes) : "memory");
}
__device__ __forceinline__ void mbar_wait(uint32_t mbar, uint32_t parity) {
    asm volatile(
        "{\n\t"
        ".reg .pred P1;\n\t"
        "WAIT_LOOP_%=:\n\t"
        "mbarrier.try_wait.parity.acquire.cluster.shared::cta.b64 P1, [%0], %1, 0x989680;\n\t"
        "@P1 bra.uni WAIT_DONE_%=;\n\t"
        "bra.uni WAIT_LOOP_%=;\n\t"
        "WAIT_DONE_%=:\n\t"
        "}"
        :: "r"(mbar), "r"(parity) : "memory");
}
// Store one b32 into a peer CTA's smem; completion counts 4 bytes on the peer's mbarrier.
__device__ __forceinline__ void st_async_b32(uint32_t raddr, uint32_t val, uint32_t rmbar) {
    asm volatile("st.async.shared::cluster.mbarrier::complete_tx::bytes.b32 [%0], %1, [%2];"
                 :: "r"(raddr), "r"(val), "r"(rmbar) : "memory");
}
#define CLUSTER_SYNC_() do { \
    asm volatile("barrier.cluster.arrive.aligned;" ::: "memory"); \
    asm volatile("barrier.cluster.wait.aligned;" ::: "memory"); \
} while (0)

// ---------------------------------------------------------------------------
// Device scratch (no allocations allowed)
// ---------------------------------------------------------------------------
__device__ float g_pre[(size_t)B_ * S_ * H_];   // pre-activations (reused per layer)
__device__ float g_y0[(size_t)B_ * S_ * H_];    // layer-0 outputs

// ---------------------------------------------------------------------------
// GEMM: C[m,n] = sum_k Arow(m)[k] * W[n,k] + ba[n] + bb[n]   (unchanged, proven)
// ---------------------------------------------------------------------------
__global__ void __launch_bounds__(256) gemm_tn_kernel(
    const float* __restrict__ A, const int* __restrict__ idx, int lda,
    const float* __restrict__ W, const float* __restrict__ ba,
    const float* __restrict__ bb, float* __restrict__ C, int N, int K)
{
    __shared__ __align__(16) float As[16][136];
    __shared__ __align__(16) float Bs[16][136];
    __shared__ int srcs[128];

    const int tid = threadIdx.x;
    const int m0 = blockIdx.y * 128;
    const int n0 = blockIdx.x * 128;

    if (idx != nullptr && tid < 128) srcs[tid] = idx[m0 + tid];
    __syncthreads();

    const int lm = tid >> 1;
    const int lk = (tid & 1) * 8;
    const float* arow = (idx != nullptr) ? (A + (size_t)srcs[lm] * (size_t)lda)
                                         : (A + (size_t)(m0 + lm) * (size_t)lda);
    const float* brow = W + (size_t)(n0 + lm) * (size_t)K;

    const int iy = tid >> 4;
    const int ix = tid & 15;

    u64 acc[8][4];
#pragma unroll
    for (int r = 0; r < 8; ++r)
#pragma unroll
        for (int c = 0; c < 4; ++c) acc[r][c] = 0ull;

    for (int k0 = 0; k0 < K; k0 += 16) {
        float4 av0 = *(const float4*)(arow + k0 + lk);
        float4 av1 = *(const float4*)(arow + k0 + lk + 4);
        float4 bv0 = *(const float4*)(brow + k0 + lk);
        float4 bv1 = *(const float4*)(brow + k0 + lk + 4);
        __syncthreads();
        As[lk + 0][lm] = av0.x; As[lk + 1][lm] = av0.y;
        As[lk + 2][lm] = av0.z; As[lk + 3][lm] = av0.w;
        As[lk + 4][lm] = av1.x; As[lk + 5][lm] = av1.y;
        As[lk + 6][lm] = av1.z; As[lk + 7][lm] = av1.w;
        Bs[lk + 0][lm] = bv0.x; Bs[lk + 1][lm] = bv0.y;
        Bs[lk + 2][lm] = bv0.z; Bs[lk + 3][lm] = bv0.w;
        Bs[lk + 4][lm] = bv1.x; Bs[lk + 5][lm] = bv1.y;
        Bs[lk + 6][lm] = bv1.z; Bs[lk + 7][lm] = bv1.w;
        __syncthreads();
#pragma unroll
        for (int k = 0; k < 16; ++k) {
            float4 a0 = *(const float4*)&As[k][iy * 8];
            float4 a1 = *(const float4*)&As[k][iy * 8 + 4];
            ulonglong2 bq0 = *(const ulonglong2*)&Bs[k][ix * 8];
            ulonglong2 bq1 = *(const ulonglong2*)&Bs[k][ix * 8 + 4];
            u64 s;
            s = splat2(a0.x);
            fma2(acc[0][0], s, bq0.x); fma2(acc[0][1], s, bq0.y);
            fma2(acc[0][2], s, bq1.x); fma2(acc[0][3], s, bq1.y);
            s = splat2(a0.y);
            fma2(acc[1][0], s, bq0.x); fma2(acc[1][1], s, bq0.y);
            fma2(acc[1][2], s, bq1.x); fma2(acc[1][3], s, bq1.y);
            s = splat2(a0.z);
            fma2(acc[2][0], s, bq0.x); fma2(acc[2][1], s, bq0.y);
            fma2(acc[2][2], s, bq1.x); fma2(acc[2][3], s, bq1.y);
            s = splat2(a0.w);
            fma2(acc[3][0], s, bq0.x); fma2(acc[3][1], s, bq0.y);
            fma2(acc[3][2], s, bq1.x); fma2(acc[3][3], s, bq1.y);
            s = splat2(a1.x);
            fma2(acc[4][0], s, bq0.x); fma2(acc[4][1], s, bq0.y);
            fma2(acc[4][2], s, bq1.x); fma2(acc[4][3], s, bq1.y);
            s = splat2(a1.y);
            fma2(acc[5][0], s, bq0.x); fma2(acc[5][1], s, bq0.y);
            fma2(acc[5][2], s, bq1.x); fma2(acc[5][3], s, bq1.y);
            s = splat2(a1.z);
            fma2(acc[6][0], s, bq0.x); fma2(acc[6][1], s, bq0.y);
            fma2(acc[6][2], s, bq1.x); fma2(acc[6][3], s, bq1.y);
            s = splat2(a1.w);
            fma2(acc[7][0], s, bq0.x); fma2(acc[7][1], s, bq0.y);
            fma2(acc[7][2], s, bq1.x); fma2(acc[7][3], s, bq1.y);
        }
    }

    const int n = n0 + ix * 8;
    float bias[8];
#pragma unroll
    for (int c = 0; c < 8; ++c) bias[c] = ba[n + c] + bb[n + c];

#pragma unroll
    for (int r = 0; r < 8; ++r) {
        float v[8];
#pragma unroll
        for (int c = 0; c < 4; ++c) unpack2(acc[r][c], v[2 * c], v[2 * c + 1]);
        float4 o0 = make_float4(v[0] + bias[0], v[1] + bias[1], v[2] + bias[2], v[3] + bias[3]);
        float4 o1 = make_float4(v[4] + bias[4], v[5] + bias[5], v[6] + bias[6], v[7] + bias[7]);
        float* crow = C + (size_t)(m0 + iy * 8 + r) * (size_t)N + n;
        *(float4*)(crow)     = o0;
        *(float4*)(crow + 4) = o1;
    }
}

// ---------------------------------------------------------------------------
// Recurrent scan, software-pipelined over two independent 2-batch sub-problems:
//   phase(sub s): wait h_s(t-1) -> matvec -> reduce -> finalize (st.async h_s(t))
// Sub A's DSMEM flight + mbarrier completion is hidden under sub B's phase
// and vice versa. Compute map: jg = tid>>3 (2 j-rows), ks = tid&7 (64-k).
// Finalize map: sub = tid>>7, fj = tid&63, fb = (tid>>6)&1 -> one value/thread.
// Peer st.async addresses hoisted out of the loop (mapa once, parity = +offset).
// ---------------------------------------------------------------------------
__global__ void __launch_bounds__(256, 1) __cluster_dims__(CL_, 1, 1)
rnn_scan_kernel(const float* __restrict__ pre, const float* __restrict__ Whh,
                float* __restrict__ y, float* __restrict__ hlast)
{
    __shared__ __align__(16) float h_sh[2][2][HPS_];   // [sub][parity][2 rows * 544]
    __shared__ __align__(16) float red[2][8 * RP2_];   // [sub][ks][64 j * 2 lanes (+pad)]
    __shared__ __align__(8) u64 bars[2][2];            // [sub][parity]

    const int tid  = threadIdx.x;
    const int rank = blockIdx.x;   // 0..7  (j slice)
    const int bt   = blockIdx.y;   // 0..15 (batch tile)
    const int jg   = tid >> 3;     // 0..31 (2 j-rows each)
    const int ks   = tid & 7;      // 0..7  (64-k slice)

    uint32_t barAddr[2][2];
#pragma unroll
    for (int s = 0; s < 2; ++s) {
        barAddr[s][0] = smem_u32(&bars[s][0]);
        barAddr[s][1] = smem_u32(&bars[s][1]);
    }

    if (tid == 0) {
#pragma unroll
        for (int s = 0; s < 2; ++s) {
            mbar_init(barAddr[s][0], 1);
            mbar_init(barAddr[s][1], 1);
            mbar_arrive_expect_tx(barAddr[s][1], 4096);   // first use: h_1 at t=1
            mbar_arrive_expect_tx(barAddr[s][0], 4096);   // first use: h_2 at t=2
        }
    }
    // h_0 = 0 in parity-0 buffers; parity-1 fully overwritten by st.async
    for (int i = tid; i < HPS_; i += 256) { h_sh[0][0][i] = 0.f; h_sh[1][0][i] = 0.f; }
    __syncthreads();
    CLUSTER_SYNC_();   // all CTAs' mbarriers live before any st.async

    // --- W slice into registers: rows {2jg, 2jg+1}, k in [ks*64, ks*64+64) ---
    u64 wA[32], wB[32];
    {
        const float4* wa = (const float4*)(Whh + (size_t)(rank * JL_ + 2 * jg) * H_ + ks * 64);
        const float4* wb = (const float4*)(Whh + (size_t)(rank * JL_ + 2 * jg + 1) * H_ + ks * 64);
#pragma unroll
        for (int i = 0; i < 16; ++i) {
            float4 va = __ldg(wa + i);
            float4 vb = __ldg(wb + i);
            wA[2 * i] = pack2(va.x, va.y); wA[2 * i + 1] = pack2(va.z, va.w);
            wB[2 * i] = pack2(vb.x, vb.y); wB[2 * i + 1] = pack2(vb.z, vb.w);
        }
    }

    // --- finalize identity: each thread owns ONE h value of ONE sub ---
    const int sub   = tid >> 7;        // which sub-problem this thread finalizes
    const int fj    = tid & 63;        // j row within CTA slice
    const int fb    = (tid >> 6) & 1;  // batch lane within sub
    const int batch = bt * BC_ + sub * 2 + fb;
    const size_t pbase = ((size_t)batch * S_) * H_ + rank * JL_ + fj;

    // mapa-hoisted peer addresses (parity 0); parity 1 = +const byte offset
    uint32_t rslot[CL_], rbar[CL_];
    {
        const uint32_t slot0 = smem_u32(&h_sh[sub][0][fb * HROW_ + rank * 68 + fj]);
        const uint32_t bar0  = barAddr[sub][0];
#pragma unroll
        for (uint32_t c = 0; c < CL_; ++c) {
            rslot[c] = mapa_(slot0, c);
            rbar[c]  = mapa_(bar0, c);
        }
    }

    for (int t = 0; t < S_; ++t) {
        const int q = t & 1;
        const uint32_t poff = ((t + 1) & 1) ? (uint32_t)(HPS_ * 4) : 0u;  // next-parity h offset
        const uint32_t boff = ((t + 1) & 1) ? 8u : 0u;                    // next-parity bar offset

#pragma unroll
        for (int s = 0; s < 2; ++s) {
            // prefetch pre[t] (only this phase's senders) before the wait
            float p = 0.f;
            if (sub == s) p = __ldg(pre + pbase + (size_t)t * H_);

            if (t > 0) {
                mbar_wait(barAddr[s][q], ((unsigned)(t - 1) >> 1) & 1);
                if (tid == 0 && t + 2 < S_)
                    mbar_arrive_expect_tx(barAddr[s][q], 4096);   // re-arm for t+2
            }

            // --- matvec: 2 j-rows x 2 lanes over this thread's 64 k ---
            const float* hb = h_sh[s][q];
            const char* h0 = (const char*)(hb + ks * 68);            // lane 0
            const char* h1 = (const char*)(hb + HROW_ + ks * 68);    // lane 1
            u64 a00 = 0, a01 = 0, a10 = 0, a11 = 0;  // [rowA/B][lane0/1]
#pragma unroll
            for (int ii = 0; ii < 16; ++ii) {
                ulonglong2 x0 = *(const ulonglong2*)(h0 + ii * 16);
                ulonglong2 x1 = *(const ulonglong2*)(h1 + ii * 16);
                const u64 wa0 = wA[2 * ii], wa1 = wA[2 * ii + 1];
                const u64 wb0 = wB[2 * ii], wb1 = wB[2 * ii + 1];
                fma2(a00, wa0, x0.x); fma2(a00, wa1, x0.y);
                fma2(a01, wa0, x1.x); fma2(a01, wa1, x1.y);
                fma2(a10, wb0, x0.x); fma2(a10, wb1, x0.y);
                fma2(a11, wb0, x1.x); fma2(a11, wb1, x1.y);
            }

            // fold k-pair halves -> 4 scalars; layout word = row*2 + lane
            float lo, hi;
            float4 v4;
            unpack2(a00, lo, hi); v4.x = lo + hi;   // row 2jg,   lane 0
            unpack2(a01, lo, hi); v4.y = lo + hi;   // row 2jg,   lane 1
            unpack2(a10, lo, hi); v4.z = lo + hi;   // row 2jg+1, lane 0
            unpack2(a11, lo, hi); v4.w = lo + hi;   // row 2jg+1, lane 1
            *(float4*)&red[s][ks * RP2_ + 4 * jg] = v4;   // RP2_ multiple of 4 -> aligned
            __syncthreads();

            // --- finalize: this sub's 128 owner threads ---
            if (sub == s) {
                float acc = p;
#pragma unroll
                for (int g = 0; g < 8; ++g) acc += red[s][g * RP2_ + fj * 2 + fb];
                const float v = fast_tanh(acc);
                y[pbase + (size_t)t * H_] = v;
                if (t == S_ - 1) {
                    hlast[(size_t)batch * H_ + rank * JL_ + fj] = v;
                } else {
                    const uint32_t uv = __float_as_uint(v);
#pragma unroll
                    for (uint32_t c = 0; c < CL_; ++c)
                        st_async_b32(rslot[c] + poff, uv, rbar[c] + boff);
                }
            }
        }
    }
}

// ---------------------------------------------------------------------------
// Launch
// Inputs: src, emb, W_ih0, W_hh0, b_ih0, b_hh0, W_ih1, W_hh1, b_ih1, b_hh1
// Output: y1 [B,S,H] followed by hidden [2,B,H]
// ---------------------------------------------------------------------------
extern "C" void kernel_launch(void* const* d_in, const int* in_sizes, int n_in,
                              void* d_out, int out_size)
{
    (void)in_sizes; (void)n_in; (void)out_size;
    const int*   src  = (const int*)d_in[0];
    const float* emb  = (const float*)d_in[1];
    const float* Wih0 = (const float*)d_in[2];
    const float* Whh0 = (const float*)d_in[3];
    const float* bih0 = (const float*)d_in[4];
    const float* bhh0 = (const float*)d_in[5];
    const float* Wih1 = (const float*)d_in[6];
    const float* Whh1 = (const float*)d_in[7];
    const float* bih1 = (const float*)d_in[8];
    const float* bhh1 = (const float*)d_in[9];

    float* out = (float*)d_out;
    float* y1  = out;
    float* hid = out + (size_t)B_ * S_ * H_;

    float *pre = nullptr, *y0 = nullptr;
    cudaGetSymbolAddress((void**)&pre, g_pre);
    cudaGetSymbolAddress((void**)&y0,  g_y0);

    const dim3 gemm_blk(256);
    const dim3 scan_blk(256);
    const dim3 gemm_grid(H_ / 128, (B_ * S_) / 128);
    const dim3 scan_grid(CL_, BT_);

    // Layer 0: fused embedding-gather GEMM -> pre, then scan -> y0, h_last0
    gemm_tn_kernel<<<gemm_grid, gemm_blk>>>(emb, src, E_, Wih0, bih0, bhh0, pre, H_, E_);
    rnn_scan_kernel<<<scan_grid, scan_blk>>>(pre, Whh0, y0, hid);

    // Layer 1: plain GEMM -> pre (reused), then scan -> y1 (d_out), h_last1
    gemm_tn_kernel<<<gemm_grid, gemm_blk>>>(y0, nullptr, H_, Wih1, bih1, bhh1, pre, H_, H_);
    rnn_scan_kernel<<<scan_grid, scan_blk>>>(pre, Whh1, y1, hid + (size_t)B_ * H_);
}